// round 15
// baseline (speedup 1.0000x reference)
#include <cuda_runtime.h>
#include <cuda_fp16.h>
#include <math.h>
#include <stdint.h>

// ---------------------------------------------------------------------------
// Problem constants: D=512, H=8, hd=64. T runtime (6144 in the fixed setup).
// ---------------------------------------------------------------------------
#define MAX_T 8192
#define MAX_TILES 1024
#define LOG2E 1.44269504088896f

// Scratch (device globals; no allocation allowed)
__device__ __half g_h16  [MAX_T * 512];    // fp16 h_n; reused as proj16 output
__device__ __half g_qkv16[MAX_T * 1536];   // q(x0.125*log2e) | k | v per token
__device__ __half g_ctx16[MAX_T * 512];
__device__ __half g_h1h  [MAX_T * 512];    // fp16 h1 (ffn1 A operand)
__device__ __half g_mid16[MAX_T * 2048];
__device__ float  g_parts[MAX_T * 1024];   // attn O partials / ffn2 partials
__device__ float  g_h1   [MAX_T * 512];
__device__ __half g_wt16 [3145728];        // transposed weights [N,K] fp16
__device__ float  g_bqkv [1536];           // packed qkv bias
__device__ float  g_pm   [2 * MAX_T * 8];  // attn partial row-max (base-2)
__device__ float  g_pl   [2 * MAX_T * 8];  // attn partial row-sum; slot1<0 = skip
__device__ int    g_tiles[MAX_TILES * 8];  // jobs: qstart,qlen,ks,kl,slot,nparts
__device__ int    g_meta[4];

#define WT_QKV  0                          // [1536, 512]
#define WT_PROJ 786432
#define WT_FFN1 1048576
#define WT_FFN2 2097152

// ---------------------------------------------------------------------------
// PTX helpers (sm_80-level; none 'a'-gated)
// ---------------------------------------------------------------------------
__device__ __forceinline__ void cpa16(uint32_t dst, const void* src, int sz) {
    asm volatile("cp.async.cg.shared.global [%0], [%1], 16, %2;\n"
                 :: "r"(dst), "l"(src), "r"(sz) : "memory");
}
__device__ __forceinline__ void cp_commit() {
    asm volatile("cp.async.commit_group;\n" ::: "memory");
}
template <int N> __device__ __forceinline__ void cp_wait() {
    asm volatile("cp.async.wait_group %0;\n" :: "n"(N) : "memory");
}
__device__ __forceinline__ uint32_t smem_u32(const void* p) {
    uint32_t a;
    asm("{ .reg .u64 t; cvta.to.shared.u64 t, %1; cvt.u32.u64 %0, t; }"
        : "=r"(a) : "l"(p));
    return a;
}
__device__ __forceinline__ void ldsm_x4(uint32_t& r0, uint32_t& r1,
                                        uint32_t& r2, uint32_t& r3, uint32_t a) {
    asm volatile("ldmatrix.sync.aligned.m8n8.x4.shared.b16 {%0,%1,%2,%3}, [%4];"
                 : "=r"(r0), "=r"(r1), "=r"(r2), "=r"(r3) : "r"(a));
}
__device__ __forceinline__ void ldsm_x4_t(uint32_t& r0, uint32_t& r1,
                                          uint32_t& r2, uint32_t& r3, uint32_t a) {
    asm volatile("ldmatrix.sync.aligned.m8n8.x4.trans.shared.b16 {%0,%1,%2,%3}, [%4];"
                 : "=r"(r0), "=r"(r1), "=r"(r2), "=r"(r3) : "r"(a));
}
__device__ __forceinline__ void mma_f16(float c[4],
                                        uint32_t a0, uint32_t a1,
                                        uint32_t a2, uint32_t a3,
                                        uint32_t b0, uint32_t b1) {
    asm volatile(
        "mma.sync.aligned.m16n8k16.row.col.f32.f16.f16.f32 "
        "{%0,%1,%2,%3}, {%4,%5,%6,%7}, {%8,%9}, {%0,%1,%2,%3};"
        : "+f"(c[0]), "+f"(c[1]), "+f"(c[2]), "+f"(c[3])
        : "r"(a0), "r"(a1), "r"(a2), "r"(a3), "r"(b0), "r"(b1));
}
__device__ __forceinline__ float fex2(float x) {
    float y;
    asm("ex2.approx.f32 %0, %1;" : "=f"(y) : "f"(x));
    return y;
}
__device__ __forceinline__ uint32_t h2ex2(uint32_t x) {
    uint32_t y;
    asm("ex2.approx.f16x2 %0, %1;" : "=r"(y) : "r"(x));
    return y;
}

// ---------------------------------------------------------------------------
// Fused prologue: blocks [0,3072) weight transpose (+ bias pack),
// [3072,7168) f2h of h_n, block 7168 builds the attention JOB table
// (each q-tile x kv-chunk; kv split into <=2 balanced 128-aligned chunks).
// ---------------------------------------------------------------------------
__global__ void __launch_bounds__(256)
prologue_kernel(const float* __restrict__ w_v,
                const float* __restrict__ w_qk,
                const float* __restrict__ w_proj,
                const float* __restrict__ w_f1,
                const float* __restrict__ w_f2,
                const float* __restrict__ b_v,
                const float* __restrict__ b_qk,
                const float* __restrict__ h_n,
                __half* __restrict__ h16,
                __half* __restrict__ wt,
                float* __restrict__ bqkv,
                const int* __restrict__ cum_raw, int T) {
    __shared__ float t[32][33];
    int b = blockIdx.x;

    if (b < 3072) {
        int gi = b * 256 + threadIdx.x;
        if (gi < 1536) bqkv[gi] = (gi < 1024) ? b_qk[gi] : b_v[gi - 1024];

        const float* W; __half* Wt; int K, N;
        if (b < 512)        { W = w_qk;   Wt = wt + WT_QKV;          K = 512;  N = 1024; }
        else if (b < 768)   { W = w_v;    Wt = wt + WT_QKV + 524288; K = 512;  N = 512;  b -= 512; }
        else if (b < 1024)  { W = w_proj; Wt = wt + WT_PROJ;         K = 512;  N = 512;  b -= 768; }
        else if (b < 2048)  { W = w_f1;   Wt = wt + WT_FFN1;         K = 512;  N = 2048; b -= 1024; }
        else                { W = w_f2;   Wt = wt + WT_FFN2;         K = 2048; N = 512;  b -= 2048; }
        const int nx = N >> 5;
        const int n0 = (b % nx) * 32, k0 = (b / nx) * 32;
        const int x = threadIdx.x & 31, y = threadIdx.x >> 5;  // 32 x 8
#pragma unroll
        for (int i = 0; i < 32; i += 8)
            t[y + i][x] = W[(size_t)(k0 + y + i) * N + n0 + x];
        __syncthreads();
#pragma unroll
        for (int i = 0; i < 32; i += 8)
            Wt[(size_t)(n0 + y + i) * K + k0 + x] = __float2half_rn(t[x][y + i]);
    } else if (b < 7168) {
        int i = (b - 3072) * 256 + threadIdx.x;
        if (i < T * 128) {
            float4 v = ((const float4*)h_n)[i];
            ((__half2*)h16)[i * 2 + 0] = __floats2half2_rn(v.x, v.y);
            ((__half2*)h16)[i * 2 + 1] = __floats2half2_rn(v.z, v.w);
        }
    } else if (threadIdx.x == 0) {
        bool is64 = (cum_raw[1] == 0);
        int nt = 0;
        for (int s = 0; s < 256; ++s) {
            int start = is64 ? cum_raw[2 * s] : cum_raw[s];
            if (start >= T) break;
            int end = is64 ? cum_raw[2 * (s + 1)] : cum_raw[s + 1];
            int len = end - start;
            // kv chunking: <=512 -> 1 chunk; else 2 balanced 128-aligned chunks
            int nch  = (len > 512) ? 2 : 1;
            int half = (len > 512) ? (((len + 255) >> 8) << 7) : len;
            for (int q0 = 0; q0 < len && nt < MAX_TILES - 1; q0 += 128) {
                for (int c = 0; c < nch && nt < MAX_TILES; ++c) {
                    g_tiles[nt * 8 + 0] = start + q0;
                    g_tiles[nt * 8 + 1] = min(128, len - q0);
                    g_tiles[nt * 8 + 2] = start + c * half;
                    g_tiles[nt * 8 + 3] = (c == 0) ? half : (len - half);
                    g_tiles[nt * 8 + 4] = c;
                    g_tiles[nt * 8 + 5] = nch;
                    ++nt;
                }
            }
            if (end >= T) break;
        }
        g_meta[0] = nt;
    }
}

// ---------------------------------------------------------------------------
// fp16 mma.sync GEMM: C = A[M,Kstride](cols kidx*Ksub..) @ Bt^T + epilogue.
// EPI: 0 = bias -> fp16; 1 = bias+GELU -> fp16;
//      3 = bias, cols<512 x (0.125*log2e) -> fp16 (qkv);
//      4 = raw fp32 partial (split-K: out at C + blockIdx.z*M*N).
// CTA 128x128, 8 warps (each m32n64), BK=32, 3-stage cp.async ring.
// ---------------------------------------------------------------------------
#define GRS 40
#define GTILE_B (128 * GRS * 2)      // 10240 B per tile
#define GSTAGE_B (2 * GTILE_B)       // 20480 B per stage (A + B)
#define G_SMEM_BYTES (3 * GSTAGE_B)  // 61440 B

template <int EPI>
__global__ void __launch_bounds__(256, 2)
gemm_mma_kernel(const __half* __restrict__ A, const __half* __restrict__ Bt,
                const float* __restrict__ bias,
                float* __restrict__ C, __half* __restrict__ C16,
                int M, int N, int Ksub, int Kstride) {
    extern __shared__ __half smh[];
    const uint32_t sb = smem_u32(smh);
    const int tid  = threadIdx.x;
    const int warp = tid >> 5;
    const int lane = tid & 31;
    const int g  = lane >> 2;
    const int tg = lane & 3;
    const int bm = blockIdx.y * 128;
    const int bn = blockIdx.x * 128;
    const int mr = (warp >> 1) * 32;       // 0,32,64,96
    const int nc = (warp & 1) * 64;        // 0,64
    const int kidx = blockIdx.z;

    const __half* Ap  = A  + (size_t)kidx * Ksub;
    const __half* Btp = Bt + (size_t)kidx * Ksub;
    float* Cp = C + (size_t)kidx * M * N;

    float acc[2][8][4];
#pragma unroll
    for (int i = 0; i < 2; ++i)
#pragma unroll
        for (int j = 0; j < 8; ++j)
#pragma unroll
            for (int q = 0; q < 4; ++q) acc[i][j][q] = 0.f;

    const int nch = Ksub >> 5;

    auto load_chunk = [&](int c, int s) {
        const uint32_t abase = sb + (uint32_t)s * GSTAGE_B;
        const uint32_t bbase = abase + GTILE_B;
#pragma unroll
        for (int j = 0; j < 2; ++j) {
            int i = j * 256 + tid;            // 0..511
            int r = i >> 2, ch = (i & 3) * 8;
            int gr = bm + r;
            cpa16(abase + (uint32_t)(r * GRS + ch) * 2,
                  Ap + (size_t)min(gr, M - 1) * Kstride + (size_t)c * 32 + ch,
                  (gr < M) ? 16 : 0);
        }
#pragma unroll
        for (int j = 0; j < 2; ++j) {
            int i = j * 256 + tid;
            int r = i >> 2, ch = (i & 3) * 8;
            cpa16(bbase + (uint32_t)(r * GRS + ch) * 2,
                  Btp + (size_t)(bn + r) * Kstride + (size_t)c * 32 + ch, 16);
        }
        cp_commit();
    };

    load_chunk(0, 0);
    load_chunk(1, 1);

    for (int c = 0; c < nch; ++c) {
        const int s = c % 3;
        if (c + 1 < nch) cp_wait<1>(); else cp_wait<0>();
        __syncthreads();                      // chunk c visible; chunk c-1 done
        if (c + 2 < nch) load_chunk(c + 2, (c + 2) % 3);

        const uint32_t as_ = sb + (uint32_t)s * GSTAGE_B;
        const uint32_t bs_ = as_ + GTILE_B;

#pragma unroll
        for (int kk16 = 0; kk16 < 2; ++kk16) {
            const int kk = kk16 * 16;
            uint32_t af[2][4];
#pragma unroll
            for (int mb = 0; mb < 2; ++mb) {
                uint32_t addr = as_ +
                    (uint32_t)((mr + mb * 16 + (lane & 7) + 8 * ((lane >> 3) & 1)) * GRS
                               + kk + 8 * (lane >> 4)) * 2;
                ldsm_x4(af[mb][0], af[mb][1], af[mb][2], af[mb][3], addr);
            }
            uint32_t bf[8][2];
#pragma unroll
            for (int p = 0; p < 4; ++p) {
                uint32_t addr = bs_ +
                    (uint32_t)((nc + p * 16 + (lane & 7) + 8 * (lane >> 4)) * GRS
                               + kk + 8 * ((lane >> 3) & 1)) * 2;
                ldsm_x4(bf[2 * p][0], bf[2 * p][1], bf[2 * p + 1][0], bf[2 * p + 1][1], addr);
            }
#pragma unroll
            for (int mb = 0; mb < 2; ++mb)
#pragma unroll
                for (int nb = 0; nb < 8; ++nb)
                    mma_f16(acc[mb][nb], af[mb][0], af[mb][1], af[mb][2], af[mb][3],
                            bf[nb][0], bf[nb][1]);
        }
    }

    // Epilogue
#pragma unroll
    for (int mb = 0; mb < 2; ++mb) {
#pragma unroll
        for (int rh = 0; rh < 2; ++rh) {
            const int gr = bm + mr + mb * 16 + rh * 8 + g;
            if (gr >= M) continue;
#pragma unroll
            for (int nb = 0; nb < 8; ++nb) {
                const int gc = bn + nc + nb * 8 + 2 * tg;
                float c0 = acc[mb][nb][rh * 2 + 0];
                float c1 = acc[mb][nb][rh * 2 + 1];
                if (EPI == 4) {
                    *(float2*)(Cp + (size_t)gr * N + gc) = make_float2(c0, c1);
                    continue;
                }
                c0 += __ldg(bias + gc + 0);
                c1 += __ldg(bias + gc + 1);
                if (EPI == 1) {
                    c0 = 0.5f * c0 * (1.0f + erff(c0 * 0.70710678118654752f));
                    c1 = 0.5f * c1 * (1.0f + erff(c1 * 0.70710678118654752f));
                } else if (EPI == 3) {
                    if (gc < 512) { c0 *= 0.125f * LOG2E; c1 *= 0.125f * LOG2E; }
                }
                *(__half2*)(C16 + (size_t)gr * N + gc) = __floats2half2_rn(c0, c1);
            }
        }
    }
}

// ---------------------------------------------------------------------------
// fp16 tensor-core flash attention, split-KV jobs over packed qkv [T,1536].
// Block = (job, head): q-tile of 128 rows x one kv chunk (<=2 per tile).
// nparts==1: normalized fp16 ctx direct write (+ slot1 skip-flag).
// nparts==2: unnormalized fp32 O partial + (m,l); combine kernel merges.
// ---------------------------------------------------------------------------
#define QKVS 1536
#define AST 72
#define KTILE_B (128 * AST * 2)              // 18432 B per 128-row K or V tile
#define AOFF_V (2 * KTILE_B)                 // 36864
#define AOFF_P (4 * KTILE_B)                 // 73728
#define ATTN_SMEM_BYTES (AOFF_P + 128 * AST * 2)  // 92160 B

__global__ void __launch_bounds__(256, 2)
attn_tc_kernel(const __half* __restrict__ qkv, __half* __restrict__ ctx,
               float* __restrict__ pO0, float* __restrict__ pO1) {
    extern __shared__ __half smh[];
    const int job = blockIdx.x;
    if (job >= g_meta[0]) return;
    const int h = blockIdx.y;

    const int qstart = g_tiles[job * 8 + 0];
    const int qlen   = g_tiles[job * 8 + 1];
    const int kstart = g_tiles[job * 8 + 2];
    const int klen   = g_tiles[job * 8 + 3];
    const int slot   = g_tiles[job * 8 + 4];
    const int nparts = g_tiles[job * 8 + 5];

    const uint32_t sb  = smem_u32(smh);
    const uint32_t sbP = sb + AOFF_P;
    __half* Ps = smh + AOFF_P / 2;

    const int tid  = threadIdx.x;
    const int warp = tid >> 5;
    const int lane = tid & 31;
    const int g  = lane >> 2;
    const int tg = lane & 3;
    const int wr = warp * 16;

    // ---- Q fragments in registers (already scaled by 0.125*log2e) ----
    uint32_t qa[4][4];
    {
        const int r0 = wr + g, r1 = r0 + 8;
        const uint32_t* q0p = (const uint32_t*)(qkv + (size_t)(qstart + r0) * QKVS + h * 64);
        const uint32_t* q1p = (const uint32_t*)(qkv + (size_t)(qstart + r1) * QKVS + h * 64);
        const bool v0 = r0 < qlen, v1 = r1 < qlen;
#pragma unroll
        for (int k16 = 0; k16 < 4; ++k16) {
            qa[k16][0] = v0 ? q0p[k16 * 8 + tg]     : 0u;
            qa[k16][1] = v1 ? q1p[k16 * 8 + tg]     : 0u;
            qa[k16][2] = v0 ? q0p[k16 * 8 + tg + 4] : 0u;
            qa[k16][3] = v1 ? q1p[k16 * 8 + tg + 4] : 0u;
        }
    }

    // ---- KV tile loader (128 rows, zero-fill beyond klen) ----
    auto loadKV = [&](int kb, int s) {
        const uint32_t kbase = sb + (uint32_t)s * KTILE_B;
        const uint32_t vbase = sb + AOFF_V + (uint32_t)s * KTILE_B;
#pragma unroll
        for (int j = 0; j < 4; ++j) {
            int i = j * 256 + tid;           // 0..1023
            int r = i >> 3, c = (i & 7) * 8; // r 0..127
            int valid = (kb + r < klen) ? 16 : 0;
            size_t t = (size_t)(kstart + min(kb + r, klen - 1));
            cpa16(kbase + (uint32_t)(r * AST + c) * 2,
                  qkv + t * QKVS + 512 + h * 64 + c, valid);
            cpa16(vbase + (uint32_t)(r * AST + c) * 2,
                  qkv + t * QKVS + 1024 + h * 64 + c, valid);
        }
        cp_commit();
    };

    const int nkb = (klen + 127) >> 7;
    loadKV(0, 0);

    float O[8][4];
#pragma unroll
    for (int nb = 0; nb < 8; ++nb)
#pragma unroll
        for (int q = 0; q < 4; ++q) O[nb][q] = 0.f;
    float m0 = -1e30f, m1 = -1e30f, l0 = 0.f, l1 = 0.f;

    for (int ib = 0; ib < nkb; ++ib) {
        const int s = ib & 1;
        cp_wait<0>();
        __syncthreads();            // tile ib resident; stage s^1 fully consumed
        if (ib + 1 < nkb) loadKV((ib + 1) * 128, s ^ 1);

        for (int hb = 0; hb < 2; ++hb) {
            const int kb = ib * 128 + hb * 64;
            if (kb >= klen) break;
            const uint32_t kst = sb + (uint32_t)s * KTILE_B + (uint32_t)(hb * 64 * AST) * 2;
            const uint32_t vst = sb + AOFF_V + (uint32_t)s * KTILE_B + (uint32_t)(hb * 64 * AST) * 2;

            // ---- S' = (Q*log2e/8) @ K^T (base-2 scores) ----
            float sf[8][4];
#pragma unroll
            for (int nb = 0; nb < 8; ++nb)
#pragma unroll
                for (int q = 0; q < 4; ++q) sf[nb][q] = 0.f;

#pragma unroll
            for (int k16 = 0; k16 < 4; ++k16) {
                const int kk = k16 * 16;
                uint32_t kbf[8][2];
#pragma unroll
                for (int p = 0; p < 4; ++p) {
                    uint32_t addr = kst +
                        (uint32_t)((p * 16 + (lane & 7) + 8 * (lane >> 4)) * AST
                                   + kk + 8 * ((lane >> 3) & 1)) * 2;
                    ldsm_x4(kbf[2 * p][0], kbf[2 * p][1],
                            kbf[2 * p + 1][0], kbf[2 * p + 1][1], addr);
                }
#pragma unroll
                for (int nb = 0; nb < 8; ++nb)
                    mma_f16(sf[nb], qa[k16][0], qa[k16][1], qa[k16][2], qa[k16][3],
                            kbf[nb][0], kbf[nb][1]);
            }

            // ---- online softmax in base-2 (ex2.approx.f16x2) ----
            float mx0 = -1e30f, mx1 = -1e30f;
#pragma unroll
            for (int nb = 0; nb < 8; ++nb) {
                int c0i = kb + nb * 8 + 2 * tg;
                if (c0i     >= klen) { sf[nb][0] = -1e30f; sf[nb][2] = -1e30f; }
                if (c0i + 1 >= klen) { sf[nb][1] = -1e30f; sf[nb][3] = -1e30f; }
                mx0 = fmaxf(mx0, fmaxf(sf[nb][0], sf[nb][1]));
                mx1 = fmaxf(mx1, fmaxf(sf[nb][2], sf[nb][3]));
            }
            mx0 = fmaxf(mx0, __shfl_xor_sync(0xffffffffu, mx0, 1));
            mx0 = fmaxf(mx0, __shfl_xor_sync(0xffffffffu, mx0, 2));
            mx1 = fmaxf(mx1, __shfl_xor_sync(0xffffffffu, mx1, 1));
            mx1 = fmaxf(mx1, __shfl_xor_sync(0xffffffffu, mx1, 2));

            const float mn0 = fmaxf(m0, mx0);
            const float mn1 = fmaxf(m1, mx1);
            const float al0 = fex2(m0 - mn0);
            const float al1 = fex2(m1 - mn1);
            float sum0 = 0.f, sum1 = 0.f;
#pragma unroll
            for (int nb = 0; nb < 8; ++nb) {
                __half2 d01 = __floats2half2_rn(sf[nb][0] - mn0, sf[nb][1] - mn0);
                __half2 d23 = __floats2half2_rn(sf[nb][2] - mn1, sf[nb][3] - mn1);
                uint32_t p01 = h2ex2(*(uint32_t*)&d01);
                uint32_t p23 = h2ex2(*(uint32_t*)&d23);
                float2 f01 = __half22float2(*(__half2*)&p01);
                float2 f23 = __half22float2(*(__half2*)&p23);
                sum0 += f01.x + f01.y;
                sum1 += f23.x + f23.y;
                *(uint32_t*)&Ps[(wr + g)     * AST + nb * 8 + 2 * tg] = p01;
                *(uint32_t*)&Ps[(wr + g + 8) * AST + nb * 8 + 2 * tg] = p23;
            }
            sum0 += __shfl_xor_sync(0xffffffffu, sum0, 1);
            sum0 += __shfl_xor_sync(0xffffffffu, sum0, 2);
            sum1 += __shfl_xor_sync(0xffffffffu, sum1, 1);
            sum1 += __shfl_xor_sync(0xffffffffu, sum1, 2);
            l0 = l0 * al0 + sum0;
            l1 = l1 * al1 + sum1;
            m0 = mn0; m1 = mn1;
#pragma unroll
            for (int nb = 0; nb < 8; ++nb) {
                O[nb][0] *= al0; O[nb][1] *= al0;
                O[nb][2] *= al1; O[nb][3] *= al1;
            }
            __syncwarp();   // P rows are warp-private: order stores before ldsm

            // ---- O += P @ V ----
#pragma unroll
            for (int k16 = 0; k16 < 4; ++k16) {
                const int kk = k16 * 16;
                uint32_t pa[4];
                {
                    uint32_t addr = sbP +
                        (uint32_t)((wr + (lane & 7) + 8 * ((lane >> 3) & 1)) * AST
                                   + kk + 8 * (lane >> 4)) * 2;
                    ldsm_x4(pa[0], pa[1], pa[2], pa[3], addr);
                }
                uint32_t vbf[8][2];
#pragma unroll
                for (int p = 0; p < 4; ++p) {
                    uint32_t addr = vst +
                        (uint32_t)((kk + (lane & 15)) * AST + p * 16 + 8 * (lane >> 4)) * 2;
                    ldsm_x4_t(vbf[2 * p][0], vbf[2 * p][1],
                              vbf[2 * p + 1][0], vbf[2 * p + 1][1], addr);
                }
#pragma unroll
                for (int nb = 0; nb < 8; ++nb)
                    mma_f16(O[nb], pa[0], pa[1], pa[2], pa[3], vbf[nb][0], vbf[nb][1]);
            }
            __syncwarp();   // P reads done before next half overwrites P
        }
    }

    // ---- Output ----
    const int r0 = wr + g, r1 = r0 + 8;
    if (nparts == 1) {
        // direct normalized write; flag combine to skip these rows
        const float inv0 = 1.0f / l0;
        const float inv1 = 1.0f / l1;
#pragma unroll
        for (int nb = 0; nb < 8; ++nb) {
            const int gc = h * 64 + nb * 8 + 2 * tg;
            if (r0 < qlen)
                *(__half2*)(ctx + (size_t)(qstart + r0) * 512 + gc) =
                    __floats2half2_rn(O[nb][0] * inv0, O[nb][1] * inv0);
            if (r1 < qlen)
                *(__half2*)(ctx + (size_t)(qstart + r1) * 512 + gc) =
                    __floats2half2_rn(O[nb][2] * inv1, O[nb][3] * inv1);
        }
        if (tid < 128 && tid < qlen)
            g_pl[MAX_T * 8 + (qstart + tid) * 8 + h] = -1.f;
    } else {
        float* Op = slot ? pO1 : pO0;
#pragma unroll
        for (int nb = 0; nb < 8; ++nb) {
            const int gc = h * 64 + nb * 8 + 2 * tg;
            if (r0 < qlen)
                *(float2*)(Op + (size_t)(qstart + r0) * 512 + gc) =
                    make_float2(O[nb][0], O[nb][1]);
            if (r1 < qlen)
                *(float2*)(Op + (size_t)(qstart + r1) * 512 + gc) =
                    make_float2(O[nb][2], O[nb][3]);
        }
        if (tg == 0) {
            const int so = slot * MAX_T * 8;
            if (r0 < qlen) {
                g_pm[so + (qstart + r0) * 8 + h] = m0;
                g_pl[so + (qstart + r0) * 8 + h] = l0;
            }
            if (r1 < qlen) {
                g_pm[so + (qstart + r1) * 8 + h] = m1;
                g_pl[so + (qstart + r1) * 8 + h] = l1;
            }
        }
    }
}

// ---------------------------------------------------------------------------
// Combine split-KV partials: ctx = (O0*w0 + O1*w1) / (l0*w0 + l1*w1),
// w = 2^(m - max). Rows flagged pl1 < 0 were written directly; skip.
// ---------------------------------------------------------------------------
__global__ void __launch_bounds__(256)
attn_combine_kernel(const float* __restrict__ p0, const float* __restrict__ p1,
                    __half* __restrict__ ctx) {
    const int row = blockIdx.x;
    if (g_pl[MAX_T * 8 + row * 8] < 0.f) return;   // direct-write row
    const int tid = threadIdx.x;
    const int col = tid * 2;
    const int h = col >> 6;
    const float m0 = g_pm[row * 8 + h];
    const float m1 = g_pm[MAX_T * 8 + row * 8 + h];
    const float l0 = g_pl[row * 8 + h];
    const float l1 = g_pl[MAX_T * 8 + row * 8 + h];
    const float mf = fmaxf(m0, m1);
    const float w0 = fex2(m0 - mf);
    const float w1 = fex2(m1 - mf);
    const float inv = 1.f / (l0 * w0 + l1 * w1);
    const float2 a = *(const float2*)(p0 + (size_t)row * 512 + col);
    const float2 b = *(const float2*)(p1 + (size_t)row * 512 + col);
    *(__half2*)(ctx + (size_t)row * 512 + col) =
        __floats2half2_rn((a.x * w0 + b.x * w1) * inv,
                          (a.y * w0 + b.y * w1) * inv);
}

// ---------------------------------------------------------------------------
// Row-wise LayerNorm over D=512 of (xf [+ x16] [+ p1] [+ res] [+ bias]).
// ---------------------------------------------------------------------------
__global__ void __launch_bounds__(256)
ln_kernel(const float* __restrict__ xf, const __half* __restrict__ x16,
          const float* __restrict__ p1, const float* __restrict__ res,
          const float* __restrict__ bias,
          const float* __restrict__ g, const float* __restrict__ b,
          float* __restrict__ y, __half* __restrict__ y16) {
    const int row = blockIdx.x;
    const int tid = threadIdx.x;
    const size_t o = (size_t)row * 512;
    float v0 = 0.f, v1 = 0.f;
    if (xf)  { v0 += xf[o + tid]; v1 += xf[o + tid + 256]; }
    if (x16) { v0 += __half2float(x16[o + tid]);
               v1 += __half2float(x16[o + tid + 256]); }
    if (p1)  { v0 += p1[o + tid];  v1 += p1[o + tid + 256]; }
    if (res) { v0 += res[o + tid]; v1 += res[o + tid + 256]; }
    if (bias){ v0 += bias[tid];    v1 += bias[tid + 256]; }
    float s = v0 + v1;
    float q = v0 * v0 + v1 * v1;
#pragma unroll
    for (int off = 16; off; off >>= 1) {
        s += __shfl_xor_sync(0xffffffffu, s, off);
        q += __shfl_xor_sync(0xffffffffu, q, off);
    }
    __shared__ float ss[8], sq[8];
    int w = tid >> 5;
    if ((tid & 31) == 0) { ss[w] = s; sq[w] = q; }
    __syncthreads();
    if (tid < 32) {
        float s2 = (tid < 8) ? ss[tid] : 0.f;
        float q2 = (tid < 8) ? sq[tid] : 0.f;
#pragma unroll
        for (int off = 4; off; off >>= 1) {
            s2 += __shfl_xor_sync(0xffffffffu, s2, off);
            q2 += __shfl_xor_sync(0xffffffffu, q2, off);
        }
        if (tid == 0) { ss[0] = s2; sq[0] = q2; }
    }
    __syncthreads();
    float mean = ss[0] * (1.0f / 512.0f);
    float var  = sq[0] * (1.0f / 512.0f) - mean * mean;
    float rstd = rsqrtf(var + 1e-5f);
    float o0 = (v0 - mean) * rstd * g[tid]       + b[tid];
    float o1 = (v1 - mean) * rstd * g[tid + 256] + b[tid + 256];
    y[o + tid]       = o0;
    y[o + tid + 256] = o1;
    if (y16) {
        y16[o + tid]       = __float2half_rn(o0);
        y16[o + tid + 256] = __float2half_rn(o1);
    }
}

// ---------------------------------------------------------------------------
// Launch
// ---------------------------------------------------------------------------
extern "C" void kernel_launch(void* const* d_in, const int* in_sizes, int n_in,
                              void* d_out, int out_size) {
    const float* h_n     = (const float*)d_in[0];
    const float* to_v_w  = (const float*)d_in[1];
    const float* to_v_b  = (const float*)d_in[2];
    const float* to_qk_w = (const float*)d_in[3];
    const float* to_qk_b = (const float*)d_in[4];
    const float* proj_w  = (const float*)d_in[5];
    const float* proj_b  = (const float*)d_in[6];
    const float* ffn_w1  = (const float*)d_in[7];
    const float* ffn_b1  = (const float*)d_in[8];
    const float* ffn_w2  = (const float*)d_in[9];
    const float* ffn_b2  = (const float*)d_in[10];
    const float* ln1_g   = (const float*)d_in[11];
    const float* ln1_b   = (const float*)d_in[12];
    const float* ln2_g   = (const float*)d_in[13];
    const float* ln2_b   = (const float*)d_in[14];
    const int*   cum     = (const int*)d_in[15];

    const int T = in_sizes[0] / 512;
    if (T <= 0 || T > MAX_T) return;

    __half *h16, *qkv16, *ctx16, *h1h, *mid16, *wt;
    float *parts, *h1, *bqkv;
    cudaGetSymbolAddress((void**)&h16,   g_h16);
    cudaGetSymbolAddress((void**)&qkv16, g_qkv16);
    cudaGetSymbolAddress((void**)&ctx16, g_ctx16);
    cudaGetSymbolAddress((void**)&h1h,   g_h1h);
    cudaGetSymbolAddress((void**)&mid16, g_mid16);
    cudaGetSymbolAddress((void**)&wt,    g_wt16);
    cudaGetSymbolAddress((void**)&parts, g_parts);
    cudaGetSymbolAddress((void**)&h1,    g_h1);
    cudaGetSymbolAddress((void**)&bqkv,  g_bqkv);

    static bool attr_done = false;
    if (!attr_done) {
        cudaFuncSetAttribute(gemm_mma_kernel<0>,
            cudaFuncAttributeMaxDynamicSharedMemorySize, G_SMEM_BYTES);
        cudaFuncSetAttribute(gemm_mma_kernel<1>,
            cudaFuncAttributeMaxDynamicSharedMemorySize, G_SMEM_BYTES);
        cudaFuncSetAttribute(gemm_mma_kernel<3>,
            cudaFuncAttributeMaxDynamicSharedMemorySize, G_SMEM_BYTES);
        cudaFuncSetAttribute(gemm_mma_kernel<4>,
            cudaFuncAttributeMaxDynamicSharedMemorySize, G_SMEM_BYTES);
        cudaFuncSetAttribute(attn_tc_kernel,
            cudaFuncAttributeMaxDynamicSharedMemorySize, ATTN_SMEM_BYTES);
        attr_done = true;
    }

    const int MB = (T + 127) / 128;
    float* part1 = parts + (size_t)T * 512;

    // 0) fused prologue: transposes + bias pack + f2h + split-KV job table
    prologue_kernel<<<7169, 256>>>(to_v_w, to_qk_w, proj_w, ffn_w1, ffn_w2,
                                   to_v_b, to_qk_b, h_n, h16, wt, bqkv, cum, T);

    // 1) qkv16 = h @ [Wqk|Wv] + b (q cols x 0.125*log2e)
    gemm_mma_kernel<3><<<dim3(12, MB, 1), 256, G_SMEM_BYTES>>>(
        h16, wt + WT_QKV, bqkv, nullptr, qkv16, T, 1536, 512, 512);

    // 2) attention: split-KV jobs + combine
    {
        int gx = 2 * MB + 8;
        attn_tc_kernel<<<dim3(gx, 8), 256, ATTN_SMEM_BYTES>>>(qkv16, ctx16,
                                                              parts, part1);
        attn_combine_kernel<<<T, 256>>>(parts, part1, ctx16);
    }

    // 3) proj16 = ctx @ Wp + b (fp16, reuses h16) ; h1 = LN1(proj16 + h_n)
    gemm_mma_kernel<0><<<dim3(4, MB, 1), 256, G_SMEM_BYTES>>>(
        ctx16, wt + WT_PROJ, proj_b, nullptr, h16, T, 512, 512, 512);
    ln_kernel<<<T, 256>>>(nullptr, h16, nullptr, h_n, nullptr,
                          ln1_g, ln1_b, h1, h1h);

    // 4) mid16 = gelu(h1 @ W1 + b1)
    gemm_mma_kernel<1><<<dim3(16, MB, 1), 256, G_SMEM_BYTES>>>(
        h1h, wt + WT_FFN1, ffn_b1, nullptr, mid16, T, 2048, 512, 512);

    // 5) ffn2 split-K=2 -> partials ; LN2 sums p0+p1+h1+ffn_b2
    gemm_mma_kernel<4><<<dim3(4, MB, 2), 256, G_SMEM_BYTES>>>(
        mid16, wt + WT_FFN2, nullptr, parts, nullptr, T, 512, 1024, 2048);
    ln_kernel<<<T, 256>>>(parts, nullptr, part1, h1, ffn_b2,
                          ln2_g, ln2_b, (float*)d_out, nullptr);
}

// round 16
// speedup vs baseline: 1.0248x; 1.0248x over previous
#include <cuda_runtime.h>
#include <cuda_fp16.h>
#include <math.h>
#include <stdint.h>

// ---------------------------------------------------------------------------
// Problem constants: D=512, H=8, hd=64. T runtime (6144 in the fixed setup).
// ---------------------------------------------------------------------------
#define MAX_T 8192
#define MAX_TILES 1024
#define LOG2E 1.44269504088896f

// Scratch (device globals; no allocation allowed)
__device__ __half g_h16  [MAX_T * 512];    // fp16 h_n; reused as proj16 output
__device__ __half g_qkv16[MAX_T * 1536];   // q(x0.125*log2e) | k | v per token
__device__ __half g_ctx16[MAX_T * 512];
__device__ __half g_h1h  [MAX_T * 512];    // fp16 h1 (ffn1 A operand)
__device__ __half g_mid16[MAX_T * 2048];
__device__ float  g_parts[MAX_T * 1024];   // split-K partials: [2][T*512]
__device__ float  g_h1   [MAX_T * 512];
__device__ __half g_wt16 [3145728];        // transposed weights [N,K] fp16
__device__ float  g_bqkv [1536];           // packed qkv bias
__device__ int    g_tiles[MAX_TILES * 4];  // (qstart, qlen, kstart, klen)
__device__ int    g_meta[4];

#define WT_QKV  0                          // [1536, 512]
#define WT_PROJ 786432
#define WT_FFN1 1048576
#define WT_FFN2 2097152

// ---------------------------------------------------------------------------
// PTX helpers (sm_80-level; none 'a'-gated)
// ---------------------------------------------------------------------------
__device__ __forceinline__ void cpa16(uint32_t dst, const void* src, int sz) {
    asm volatile("cp.async.cg.shared.global [%0], [%1], 16, %2;\n"
                 :: "r"(dst), "l"(src), "r"(sz) : "memory");
}
__device__ __forceinline__ void cp_commit() {
    asm volatile("cp.async.commit_group;\n" ::: "memory");
}
template <int N> __device__ __forceinline__ void cp_wait() {
    asm volatile("cp.async.wait_group %0;\n" :: "n"(N) : "memory");
}
__device__ __forceinline__ uint32_t smem_u32(const void* p) {
    uint32_t a;
    asm("{ .reg .u64 t; cvta.to.shared.u64 t, %1; cvt.u32.u64 %0, t; }"
        : "=r"(a) : "l"(p));
    return a;
}
__device__ __forceinline__ void ldsm_x4(uint32_t& r0, uint32_t& r1,
                                        uint32_t& r2, uint32_t& r3, uint32_t a) {
    asm volatile("ldmatrix.sync.aligned.m8n8.x4.shared.b16 {%0,%1,%2,%3}, [%4];"
                 : "=r"(r0), "=r"(r1), "=r"(r2), "=r"(r3) : "r"(a));
}
__device__ __forceinline__ void ldsm_x4_t(uint32_t& r0, uint32_t& r1,
                                          uint32_t& r2, uint32_t& r3, uint32_t a) {
    asm volatile("ldmatrix.sync.aligned.m8n8.x4.trans.shared.b16 {%0,%1,%2,%3}, [%4];"
                 : "=r"(r0), "=r"(r1), "=r"(r2), "=r"(r3) : "r"(a));
}
__device__ __forceinline__ void mma_f16(float c[4],
                                        uint32_t a0, uint32_t a1,
                                        uint32_t a2, uint32_t a3,
                                        uint32_t b0, uint32_t b1) {
    asm volatile(
        "mma.sync.aligned.m16n8k16.row.col.f32.f16.f16.f32 "
        "{%0,%1,%2,%3}, {%4,%5,%6,%7}, {%8,%9}, {%0,%1,%2,%3};"
        : "+f"(c[0]), "+f"(c[1]), "+f"(c[2]), "+f"(c[3])
        : "r"(a0), "r"(a1), "r"(a2), "r"(a3), "r"(b0), "r"(b1));
}
__device__ __forceinline__ float fex2(float x) {
    float y;
    asm("ex2.approx.f32 %0, %1;" : "=f"(y) : "f"(x));
    return y;
}
__device__ __forceinline__ uint32_t h2ex2(uint32_t x) {
    uint32_t y;
    asm("ex2.approx.f16x2 %0, %1;" : "=r"(y) : "r"(x));
    return y;
}

// ---------------------------------------------------------------------------
// Fused prologue: blocks [0,3072) weight transpose (+ bias pack),
// [3072,7168) f2h of h_n, block 7168 builds the attention tile table.
// ---------------------------------------------------------------------------
__global__ void __launch_bounds__(256)
prologue_kernel(const float* __restrict__ w_v,
                const float* __restrict__ w_qk,
                const float* __restrict__ w_proj,
                const float* __restrict__ w_f1,
                const float* __restrict__ w_f2,
                const float* __restrict__ b_v,
                const float* __restrict__ b_qk,
                const float* __restrict__ h_n,
                __half* __restrict__ h16,
                __half* __restrict__ wt,
                float* __restrict__ bqkv,
                const int* __restrict__ cum_raw, int T) {
    __shared__ float t[32][33];
    int b = blockIdx.x;

    if (b < 3072) {
        int gi = b * 256 + threadIdx.x;
        if (gi < 1536) bqkv[gi] = (gi < 1024) ? b_qk[gi] : b_v[gi - 1024];

        const float* W; __half* Wt; int K, N;
        if (b < 512)        { W = w_qk;   Wt = wt + WT_QKV;          K = 512;  N = 1024; }
        else if (b < 768)   { W = w_v;    Wt = wt + WT_QKV + 524288; K = 512;  N = 512;  b -= 512; }
        else if (b < 1024)  { W = w_proj; Wt = wt + WT_PROJ;         K = 512;  N = 512;  b -= 768; }
        else if (b < 2048)  { W = w_f1;   Wt = wt + WT_FFN1;         K = 512;  N = 2048; b -= 1024; }
        else                { W = w_f2;   Wt = wt + WT_FFN2;         K = 2048; N = 512;  b -= 2048; }
        const int nx = N >> 5;
        const int n0 = (b % nx) * 32, k0 = (b / nx) * 32;
        const int x = threadIdx.x & 31, y = threadIdx.x >> 5;  // 32 x 8
#pragma unroll
        for (int i = 0; i < 32; i += 8)
            t[y + i][x] = W[(size_t)(k0 + y + i) * N + n0 + x];
        __syncthreads();
#pragma unroll
        for (int i = 0; i < 32; i += 8)
            Wt[(size_t)(n0 + y + i) * K + k0 + x] = __float2half_rn(t[x][y + i]);
    } else if (b < 7168) {
        int i = (b - 3072) * 256 + threadIdx.x;
        if (i < T * 128) {
            float4 v = ((const float4*)h_n)[i];
            ((__half2*)h16)[i * 2 + 0] = __floats2half2_rn(v.x, v.y);
            ((__half2*)h16)[i * 2 + 1] = __floats2half2_rn(v.z, v.w);
        }
    } else if (threadIdx.x == 0) {
        bool is64 = (cum_raw[1] == 0);
        int nt = 0;
        for (int s = 0; s < 256; ++s) {
            int start = is64 ? cum_raw[2 * s] : cum_raw[s];
            if (start >= T) break;
            int end = is64 ? cum_raw[2 * (s + 1)] : cum_raw[s + 1];
            int len = end - start;
            for (int q0 = 0; q0 < len && nt < MAX_TILES; q0 += 128) {
                g_tiles[nt * 4 + 0] = start + q0;
                g_tiles[nt * 4 + 1] = min(128, len - q0);
                g_tiles[nt * 4 + 2] = start;
                g_tiles[nt * 4 + 3] = len;
                ++nt;
            }
            if (end >= T) break;
        }
        g_meta[0] = nt;
    }
}

// ---------------------------------------------------------------------------
// fp16 mma.sync GEMM: C = A[M,Kstride](cols kidx*Ksub..) @ Bt^T + epilogue.
// EPI: 0 = bias -> fp16; 1 = bias+GELU -> fp16;
//      3 = bias, cols<512 x (0.125*log2e) -> fp16 (qkv);
//      4 = raw fp32 partial (split-K: out at C + blockIdx.z*M*N).
// CTA 128x128, 8 warps (each m32n64), BK=32, 3-stage cp.async ring, one sync
// per chunk. Smem row stride 40 halfs (conflict-free).
// ---------------------------------------------------------------------------
#define GRS 40
#define GTILE_B (128 * GRS * 2)      // 10240 B per tile
#define GSTAGE_B (2 * GTILE_B)       // 20480 B per stage (A + B)
#define G_SMEM_BYTES (3 * GSTAGE_B)  // 61440 B

template <int EPI>
__global__ void __launch_bounds__(256, 2)
gemm_mma_kernel(const __half* __restrict__ A, const __half* __restrict__ Bt,
                const float* __restrict__ bias,
                float* __restrict__ C, __half* __restrict__ C16,
                int M, int N, int Ksub, int Kstride) {
    extern __shared__ __half smh[];
    const uint32_t sb = smem_u32(smh);
    const int tid  = threadIdx.x;
    const int warp = tid >> 5;
    const int lane = tid & 31;
    const int g  = lane >> 2;
    const int tg = lane & 3;
    const int bm = blockIdx.y * 128;
    const int bn = blockIdx.x * 128;
    const int mr = (warp >> 1) * 32;       // 0,32,64,96
    const int nc = (warp & 1) * 64;        // 0,64
    const int kidx = blockIdx.z;

    const __half* Ap  = A  + (size_t)kidx * Ksub;
    const __half* Btp = Bt + (size_t)kidx * Ksub;
    float* Cp = C + (size_t)kidx * M * N;

    float acc[2][8][4];
#pragma unroll
    for (int i = 0; i < 2; ++i)
#pragma unroll
        for (int j = 0; j < 8; ++j)
#pragma unroll
            for (int q = 0; q < 4; ++q) acc[i][j][q] = 0.f;

    const int nch = Ksub >> 5;

    auto load_chunk = [&](int c, int s) {
        const uint32_t abase = sb + (uint32_t)s * GSTAGE_B;
        const uint32_t bbase = abase + GTILE_B;
#pragma unroll
        for (int j = 0; j < 2; ++j) {
            int i = j * 256 + tid;            // 0..511
            int r = i >> 2, ch = (i & 3) * 8;
            int gr = bm + r;
            cpa16(abase + (uint32_t)(r * GRS + ch) * 2,
                  Ap + (size_t)min(gr, M - 1) * Kstride + (size_t)c * 32 + ch,
                  (gr < M) ? 16 : 0);
        }
#pragma unroll
        for (int j = 0; j < 2; ++j) {
            int i = j * 256 + tid;
            int r = i >> 2, ch = (i & 3) * 8;
            cpa16(bbase + (uint32_t)(r * GRS + ch) * 2,
                  Btp + (size_t)(bn + r) * Kstride + (size_t)c * 32 + ch, 16);
        }
        cp_commit();
    };

    load_chunk(0, 0);
    load_chunk(1, 1);

    for (int c = 0; c < nch; ++c) {
        const int s = c % 3;
        if (c + 1 < nch) cp_wait<1>(); else cp_wait<0>();
        __syncthreads();                      // chunk c visible; chunk c-1 done
        if (c + 2 < nch) load_chunk(c + 2, (c + 2) % 3);

        const uint32_t as_ = sb + (uint32_t)s * GSTAGE_B;
        const uint32_t bs_ = as_ + GTILE_B;

#pragma unroll
        for (int kk16 = 0; kk16 < 2; ++kk16) {
            const int kk = kk16 * 16;
            uint32_t af[2][4];
#pragma unroll
            for (int mb = 0; mb < 2; ++mb) {
                uint32_t addr = as_ +
                    (uint32_t)((mr + mb * 16 + (lane & 7) + 8 * ((lane >> 3) & 1)) * GRS
                               + kk + 8 * (lane >> 4)) * 2;
                ldsm_x4(af[mb][0], af[mb][1], af[mb][2], af[mb][3], addr);
            }
            uint32_t bf[8][2];
#pragma unroll
            for (int p = 0; p < 4; ++p) {
                uint32_t addr = bs_ +
                    (uint32_t)((nc + p * 16 + (lane & 7) + 8 * (lane >> 4)) * GRS
                               + kk + 8 * ((lane >> 3) & 1)) * 2;
                ldsm_x4(bf[2 * p][0], bf[2 * p][1], bf[2 * p + 1][0], bf[2 * p + 1][1], addr);
            }
#pragma unroll
            for (int mb = 0; mb < 2; ++mb)
#pragma unroll
                for (int nb = 0; nb < 8; ++nb)
                    mma_f16(acc[mb][nb], af[mb][0], af[mb][1], af[mb][2], af[mb][3],
                            bf[nb][0], bf[nb][1]);
        }
    }

    // Epilogue
#pragma unroll
    for (int mb = 0; mb < 2; ++mb) {
#pragma unroll
        for (int rh = 0; rh < 2; ++rh) {
            const int gr = bm + mr + mb * 16 + rh * 8 + g;
            if (gr >= M) continue;
#pragma unroll
            for (int nb = 0; nb < 8; ++nb) {
                const int gc = bn + nc + nb * 8 + 2 * tg;
                float c0 = acc[mb][nb][rh * 2 + 0];
                float c1 = acc[mb][nb][rh * 2 + 1];
                if (EPI == 4) {
                    *(float2*)(Cp + (size_t)gr * N + gc) = make_float2(c0, c1);
                    continue;
                }
                c0 += __ldg(bias + gc + 0);
                c1 += __ldg(bias + gc + 1);
                if (EPI == 1) {
                    c0 = 0.5f * c0 * (1.0f + erff(c0 * 0.70710678118654752f));
                    c1 = 0.5f * c1 * (1.0f + erff(c1 * 0.70710678118654752f));
                } else if (EPI == 3) {
                    if (gc < 512) { c0 *= 0.125f * LOG2E; c1 *= 0.125f * LOG2E; }
                }
                *(__half2*)(C16 + (size_t)gr * N + gc) = __floats2half2_rn(c0, c1);
            }
        }
    }
}

// ---------------------------------------------------------------------------
// fp16 tensor-core flash attention over packed qkv [T,1536] (R14 version:
// single pass per q-tile, 128-row KV stages, one sync per 128 kv cols).
// ---------------------------------------------------------------------------
#define QKVS 1536
#define AST 72
#define KTILE_B (128 * AST * 2)              // 18432 B per 128-row K or V tile
#define AOFF_V (2 * KTILE_B)                 // 36864
#define AOFF_P (4 * KTILE_B)                 // 73728
#define ATTN_SMEM_BYTES (AOFF_P + 128 * AST * 2)  // 92160 B

__global__ void __launch_bounds__(256, 2)
attn_tc_kernel(const __half* __restrict__ qkv, __half* __restrict__ ctx) {
    extern __shared__ __half smh[];
    const int tile = blockIdx.x;
    if (tile >= g_meta[0]) return;
    const int h = blockIdx.y;

    const int qstart = g_tiles[tile * 4 + 0];
    const int qlen   = g_tiles[tile * 4 + 1];
    const int kstart = g_tiles[tile * 4 + 2];
    const int klen   = g_tiles[tile * 4 + 3];

    const uint32_t sb  = smem_u32(smh);
    const uint32_t sbP = sb + AOFF_P;
    __half* Ps = smh + AOFF_P / 2;

    const int tid  = threadIdx.x;
    const int warp = tid >> 5;
    const int lane = tid & 31;
    const int g  = lane >> 2;
    const int tg = lane & 3;
    const int wr = warp * 16;

    // ---- Q fragments in registers (already scaled by 0.125*log2e) ----
    uint32_t qa[4][4];
    {
        const int r0 = wr + g, r1 = r0 + 8;
        const uint32_t* q0p = (const uint32_t*)(qkv + (size_t)(qstart + r0) * QKVS + h * 64);
        const uint32_t* q1p = (const uint32_t*)(qkv + (size_t)(qstart + r1) * QKVS + h * 64);
        const bool v0 = r0 < qlen, v1 = r1 < qlen;
#pragma unroll
        for (int k16 = 0; k16 < 4; ++k16) {
            qa[k16][0] = v0 ? q0p[k16 * 8 + tg]     : 0u;
            qa[k16][1] = v1 ? q1p[k16 * 8 + tg]     : 0u;
            qa[k16][2] = v0 ? q0p[k16 * 8 + tg + 4] : 0u;
            qa[k16][3] = v1 ? q1p[k16 * 8 + tg + 4] : 0u;
        }
    }

    // ---- KV tile loader (128 rows, zero-fill beyond klen) ----
    auto loadKV = [&](int kb, int s) {
        const uint32_t kbase = sb + (uint32_t)s * KTILE_B;
        const uint32_t vbase = sb + AOFF_V + (uint32_t)s * KTILE_B;
#pragma unroll
        for (int j = 0; j < 4; ++j) {
            int i = j * 256 + tid;           // 0..1023
            int r = i >> 3, c = (i & 7) * 8; // r 0..127
            int valid = (kb + r < klen) ? 16 : 0;
            size_t t = (size_t)(kstart + min(kb + r, klen - 1));
            cpa16(kbase + (uint32_t)(r * AST + c) * 2,
                  qkv + t * QKVS + 512 + h * 64 + c, valid);
            cpa16(vbase + (uint32_t)(r * AST + c) * 2,
                  qkv + t * QKVS + 1024 + h * 64 + c, valid);
        }
        cp_commit();
    };

    const int nkb = (klen + 127) >> 7;
    loadKV(0, 0);

    float O[8][4];
#pragma unroll
    for (int nb = 0; nb < 8; ++nb)
#pragma unroll
        for (int q = 0; q < 4; ++q) O[nb][q] = 0.f;
    float m0 = -1e30f, m1 = -1e30f, l0 = 0.f, l1 = 0.f;

    for (int ib = 0; ib < nkb; ++ib) {
        const int s = ib & 1;
        cp_wait<0>();
        __syncthreads();            // tile ib resident; stage s^1 fully consumed
        if (ib + 1 < nkb) loadKV((ib + 1) * 128, s ^ 1);

        for (int hb = 0; hb < 2; ++hb) {
            const int kb = ib * 128 + hb * 64;
            if (kb >= klen) break;
            const uint32_t kst = sb + (uint32_t)s * KTILE_B + (uint32_t)(hb * 64 * AST) * 2;
            const uint32_t vst = sb + AOFF_V + (uint32_t)s * KTILE_B + (uint32_t)(hb * 64 * AST) * 2;

            // ---- S' = (Q*log2e/8) @ K^T (base-2 scores) ----
            float sf[8][4];
#pragma unroll
            for (int nb = 0; nb < 8; ++nb)
#pragma unroll
                for (int q = 0; q < 4; ++q) sf[nb][q] = 0.f;

#pragma unroll
            for (int k16 = 0; k16 < 4; ++k16) {
                const int kk = k16 * 16;
                uint32_t kbf[8][2];
#pragma unroll
                for (int p = 0; p < 4; ++p) {
                    uint32_t addr = kst +
                        (uint32_t)((p * 16 + (lane & 7) + 8 * (lane >> 4)) * AST
                                   + kk + 8 * ((lane >> 3) & 1)) * 2;
                    ldsm_x4(kbf[2 * p][0], kbf[2 * p][1],
                            kbf[2 * p + 1][0], kbf[2 * p + 1][1], addr);
                }
#pragma unroll
                for (int nb = 0; nb < 8; ++nb)
                    mma_f16(sf[nb], qa[k16][0], qa[k16][1], qa[k16][2], qa[k16][3],
                            kbf[nb][0], kbf[nb][1]);
            }

            // ---- online softmax in base-2 (ex2.approx.f16x2) ----
            float mx0 = -1e30f, mx1 = -1e30f;
#pragma unroll
            for (int nb = 0; nb < 8; ++nb) {
                int c0i = kb + nb * 8 + 2 * tg;
                if (c0i     >= klen) { sf[nb][0] = -1e30f; sf[nb][2] = -1e30f; }
                if (c0i + 1 >= klen) { sf[nb][1] = -1e30f; sf[nb][3] = -1e30f; }
                mx0 = fmaxf(mx0, fmaxf(sf[nb][0], sf[nb][1]));
                mx1 = fmaxf(mx1, fmaxf(sf[nb][2], sf[nb][3]));
            }
            mx0 = fmaxf(mx0, __shfl_xor_sync(0xffffffffu, mx0, 1));
            mx0 = fmaxf(mx0, __shfl_xor_sync(0xffffffffu, mx0, 2));
            mx1 = fmaxf(mx1, __shfl_xor_sync(0xffffffffu, mx1, 1));
            mx1 = fmaxf(mx1, __shfl_xor_sync(0xffffffffu, mx1, 2));

            const float mn0 = fmaxf(m0, mx0);
            const float mn1 = fmaxf(m1, mx1);
            const float al0 = fex2(m0 - mn0);
            const float al1 = fex2(m1 - mn1);
            float sum0 = 0.f, sum1 = 0.f;
#pragma unroll
            for (int nb = 0; nb < 8; ++nb) {
                __half2 d01 = __floats2half2_rn(sf[nb][0] - mn0, sf[nb][1] - mn0);
                __half2 d23 = __floats2half2_rn(sf[nb][2] - mn1, sf[nb][3] - mn1);
                uint32_t p01 = h2ex2(*(uint32_t*)&d01);
                uint32_t p23 = h2ex2(*(uint32_t*)&d23);
                float2 f01 = __half22float2(*(__half2*)&p01);
                float2 f23 = __half22float2(*(__half2*)&p23);
                sum0 += f01.x + f01.y;
                sum1 += f23.x + f23.y;
                *(uint32_t*)&Ps[(wr + g)     * AST + nb * 8 + 2 * tg] = p01;
                *(uint32_t*)&Ps[(wr + g + 8) * AST + nb * 8 + 2 * tg] = p23;
            }
            sum0 += __shfl_xor_sync(0xffffffffu, sum0, 1);
            sum0 += __shfl_xor_sync(0xffffffffu, sum0, 2);
            sum1 += __shfl_xor_sync(0xffffffffu, sum1, 1);
            sum1 += __shfl_xor_sync(0xffffffffu, sum1, 2);
            l0 = l0 * al0 + sum0;
            l1 = l1 * al1 + sum1;
            m0 = mn0; m1 = mn1;
#pragma unroll
            for (int nb = 0; nb < 8; ++nb) {
                O[nb][0] *= al0; O[nb][1] *= al0;
                O[nb][2] *= al1; O[nb][3] *= al1;
            }
            __syncwarp();   // P rows are warp-private: order stores before ldsm

            // ---- O += P @ V ----
#pragma unroll
            for (int k16 = 0; k16 < 4; ++k16) {
                const int kk = k16 * 16;
                uint32_t pa[4];
                {
                    uint32_t addr = sbP +
                        (uint32_t)((wr + (lane & 7) + 8 * ((lane >> 3) & 1)) * AST
                                   + kk + 8 * (lane >> 4)) * 2;
                    ldsm_x4(pa[0], pa[1], pa[2], pa[3], addr);
                }
                uint32_t vbf[8][2];
#pragma unroll
                for (int p = 0; p < 4; ++p) {
                    uint32_t addr = vst +
                        (uint32_t)((kk + (lane & 15)) * AST + p * 16 + 8 * (lane >> 4)) * 2;
                    ldsm_x4_t(vbf[2 * p][0], vbf[2 * p][1],
                              vbf[2 * p + 1][0], vbf[2 * p + 1][1], addr);
                }
#pragma unroll
                for (int nb = 0; nb < 8; ++nb)
                    mma_f16(O[nb], pa[0], pa[1], pa[2], pa[3], vbf[nb][0], vbf[nb][1]);
            }
            __syncwarp();   // P reads done before next half overwrites P
        }
    }

    // ---- write ctx (fp16) ----
    const float inv0 = 1.0f / l0;
    const float inv1 = 1.0f / l1;
    const int r0 = wr + g, r1 = r0 + 8;
#pragma unroll
    for (int nb = 0; nb < 8; ++nb) {
        const int gc = h * 64 + nb * 8 + 2 * tg;
        if (r0 < qlen)
            *(__half2*)(ctx + (size_t)(qstart + r0) * 512 + gc) =
                __floats2half2_rn(O[nb][0] * inv0, O[nb][1] * inv0);
        if (r1 < qlen)
            *(__half2*)(ctx + (size_t)(qstart + r1) * 512 + gc) =
                __floats2half2_rn(O[nb][2] * inv1, O[nb][3] * inv1);
    }
}

// ---------------------------------------------------------------------------
// Row-wise LayerNorm over D=512 of (xf [+ x16] [+ p1] [+ res] [+ bias]).
// ---------------------------------------------------------------------------
__global__ void __launch_bounds__(256)
ln_kernel(const float* __restrict__ xf, const __half* __restrict__ x16,
          const float* __restrict__ p1, const float* __restrict__ res,
          const float* __restrict__ bias,
          const float* __restrict__ g, const float* __restrict__ b,
          float* __restrict__ y, __half* __restrict__ y16) {
    const int row = blockIdx.x;
    const int tid = threadIdx.x;
    const size_t o = (size_t)row * 512;
    float v0 = 0.f, v1 = 0.f;
    if (xf)  { v0 += xf[o + tid]; v1 += xf[o + tid + 256]; }
    if (x16) { v0 += __half2float(x16[o + tid]);
               v1 += __half2float(x16[o + tid + 256]); }
    if (p1)  { v0 += p1[o + tid];  v1 += p1[o + tid + 256]; }
    if (res) { v0 += res[o + tid]; v1 += res[o + tid + 256]; }
    if (bias){ v0 += bias[tid];    v1 += bias[tid + 256]; }
    float s = v0 + v1;
    float q = v0 * v0 + v1 * v1;
#pragma unroll
    for (int off = 16; off; off >>= 1) {
        s += __shfl_xor_sync(0xffffffffu, s, off);
        q += __shfl_xor_sync(0xffffffffu, q, off);
    }
    __shared__ float ss[8], sq[8];
    int w = tid >> 5;
    if ((tid & 31) == 0) { ss[w] = s; sq[w] = q; }
    __syncthreads();
    if (tid < 32) {
        float s2 = (tid < 8) ? ss[tid] : 0.f;
        float q2 = (tid < 8) ? sq[tid] : 0.f;
#pragma unroll
        for (int off = 4; off; off >>= 1) {
            s2 += __shfl_xor_sync(0xffffffffu, s2, off);
            q2 += __shfl_xor_sync(0xffffffffu, q2, off);
        }
        if (tid == 0) { ss[0] = s2; sq[0] = q2; }
    }
    __syncthreads();
    float mean = ss[0] * (1.0f / 512.0f);
    float var  = sq[0] * (1.0f / 512.0f) - mean * mean;
    float rstd = rsqrtf(var + 1e-5f);
    float o0 = (v0 - mean) * rstd * g[tid]       + b[tid];
    float o1 = (v1 - mean) * rstd * g[tid + 256] + b[tid + 256];
    y[o + tid]       = o0;
    y[o + tid + 256] = o1;
    if (y16) {
        y16[o + tid]       = __float2half_rn(o0);
        y16[o + tid + 256] = __float2half_rn(o1);
    }
}

// ---------------------------------------------------------------------------
// Launch
// ---------------------------------------------------------------------------
extern "C" void kernel_launch(void* const* d_in, const int* in_sizes, int n_in,
                              void* d_out, int out_size) {
    const float* h_n     = (const float*)d_in[0];
    const float* to_v_w  = (const float*)d_in[1];
    const float* to_v_b  = (const float*)d_in[2];
    const float* to_qk_w = (const float*)d_in[3];
    const float* to_qk_b = (const float*)d_in[4];
    const float* proj_w  = (const float*)d_in[5];
    const float* proj_b  = (const float*)d_in[6];
    const float* ffn_w1  = (const float*)d_in[7];
    const float* ffn_b1  = (const float*)d_in[8];
    const float* ffn_w2  = (const float*)d_in[9];
    const float* ffn_b2  = (const float*)d_in[10];
    const float* ln1_g   = (const float*)d_in[11];
    const float* ln1_b   = (const float*)d_in[12];
    const float* ln2_g   = (const float*)d_in[13];
    const float* ln2_b   = (const float*)d_in[14];
    const int*   cum     = (const int*)d_in[15];

    const int T = in_sizes[0] / 512;
    if (T <= 0 || T > MAX_T) return;

    __half *h16, *qkv16, *ctx16, *h1h, *mid16, *wt;
    float *parts, *h1, *bqkv;
    cudaGetSymbolAddress((void**)&h16,   g_h16);
    cudaGetSymbolAddress((void**)&qkv16, g_qkv16);
    cudaGetSymbolAddress((void**)&ctx16, g_ctx16);
    cudaGetSymbolAddress((void**)&h1h,   g_h1h);
    cudaGetSymbolAddress((void**)&mid16, g_mid16);
    cudaGetSymbolAddress((void**)&wt,    g_wt16);
    cudaGetSymbolAddress((void**)&parts, g_parts);
    cudaGetSymbolAddress((void**)&h1,    g_h1);
    cudaGetSymbolAddress((void**)&bqkv,  g_bqkv);

    static bool attr_done = false;
    if (!attr_done) {
        cudaFuncSetAttribute(gemm_mma_kernel<0>,
            cudaFuncAttributeMaxDynamicSharedMemorySize, G_SMEM_BYTES);
        cudaFuncSetAttribute(gemm_mma_kernel<1>,
            cudaFuncAttributeMaxDynamicSharedMemorySize, G_SMEM_BYTES);
        cudaFuncSetAttribute(gemm_mma_kernel<3>,
            cudaFuncAttributeMaxDynamicSharedMemorySize, G_SMEM_BYTES);
        cudaFuncSetAttribute(gemm_mma_kernel<4>,
            cudaFuncAttributeMaxDynamicSharedMemorySize, G_SMEM_BYTES);
        cudaFuncSetAttribute(attn_tc_kernel,
            cudaFuncAttributeMaxDynamicSharedMemorySize, ATTN_SMEM_BYTES);
        attr_done = true;
    }

    const int MB = (T + 127) / 128;
    float* part1 = parts + (size_t)T * 512;

    // 0) fused prologue: transposes + bias pack + f2h + tile build
    prologue_kernel<<<7169, 256>>>(to_v_w, to_qk_w, proj_w, ffn_w1, ffn_w2,
                                   to_v_b, to_qk_b, h_n, h16, wt, bqkv, cum, T);

    // 1) qkv16 = h @ [Wqk|Wv] + b (q cols x 0.125*log2e)
    gemm_mma_kernel<3><<<dim3(12, MB, 1), 256, G_SMEM_BYTES>>>(
        h16, wt + WT_QKV, bqkv, nullptr, qkv16, T, 1536, 512, 512);

    // 2) attention (single pass, direct write)
    {
        int gx = (T + 127) / 128 + 8;
        attn_tc_kernel<<<dim3(gx, 8), 256, ATTN_SMEM_BYTES>>>(qkv16, ctx16);
    }

    // 3) proj16 = ctx @ Wp + b (fp16, reuses h16) ; h1 = LN1(proj16 + h_n)
    gemm_mma_kernel<0><<<dim3(4, MB, 1), 256, G_SMEM_BYTES>>>(
        ctx16, wt + WT_PROJ, proj_b, nullptr, h16, T, 512, 512, 512);
    ln_kernel<<<T, 256>>>(nullptr, h16, nullptr, h_n, nullptr,
                          ln1_g, ln1_b, h1, h1h);

    // 4) mid16 = gelu(h1 @ W1 + b1)
    gemm_mma_kernel<1><<<dim3(16, MB, 1), 256, G_SMEM_BYTES>>>(
        h1h, wt + WT_FFN1, ffn_b1, nullptr, mid16, T, 2048, 512, 512);

    // 5) ffn2 split-K=2 -> partials ; LN2 sums p0+p1+h1+ffn_b2
    gemm_mma_kernel<4><<<dim3(4, MB, 2), 256, G_SMEM_BYTES>>>(
        mid16, wt + WT_FFN2, nullptr, parts, nullptr, T, 512, 1024, 2048);
    ln_kernel<<<T, 256>>>(parts, nullptr, part1, h1, ffn_b2,
                          ln2_g, ln2_b, (float*)d_out, nullptr);
}